// round 2
// baseline (speedup 1.0000x reference)
#include <cuda_runtime.h>

#define N_NODES 20000
#define R_REL   8
#define C_IN    256
#define C_HID   256
#define C_OUT   128
#define KA      (R_REL * 256)   // 2048 aggregated-feature K
#define KTOT    (KA + 256)      // 2304 total K (agg + root/self)

// Scratch (static device globals — no runtime allocation).
__device__ float g_A[(size_t)R_REL * N_NODES * 256];  // [N][R][256]
__device__ float g_h[(size_t)N_NODES * C_HID];        // layer-1 activations
__device__ float g_inv[N_NODES * R_REL];              // counts -> 1/max(cnt,1)
__device__ int   g_is64;                              // edge index dtype flag

// ---------------------------------------------------------------------------
// Index dtype detector: if edge_index is int64, the high 32-bit word of every
// entry is 0 (indices are small non-negative). If int32, "odd words" are
// random node indices — all-zero over 128 samples is impossible.
// ---------------------------------------------------------------------------
__global__ void k_detect(const unsigned* __restrict__ ei_words, int nwords) {
    if (threadIdx.x == 0 && blockIdx.x == 0) {
        int is64 = 1;
        int lim = nwords < 256 ? nwords : 256;
        for (int i = 1; i < lim; i += 2)
            if (ei_words[i] != 0u) { is64 = 0; break; }
        g_is64 = is64;
    }
}

__device__ __forceinline__ int load_idx(const void* p, long long i, int is64) {
    return is64 ? (int)((const long long*)p)[i] : ((const int*)p)[i];
}

// ---------------------------------------------------------------------------
// Per-(dst, rel) edge counts
// ---------------------------------------------------------------------------
__global__ void k_count(const void* __restrict__ ei,
                        const void* __restrict__ et,
                        float* __restrict__ cnt, int E) {
    int e = blockIdx.x * blockDim.x + threadIdx.x;
    if (e >= E) return;
    int is64 = g_is64;
    int dst = load_idx(ei, (long long)E + e, is64);
    int r   = load_idx(et, e, is64);
    atomicAdd(&cnt[dst * R_REL + r], 1.0f);
}

__global__ void k_inv(float* __restrict__ cnt, int n) {
    int i = blockIdx.x * blockDim.x + threadIdx.x;
    if (i < n) cnt[i] = 1.0f / fmaxf(cnt[i], 1.0f);
}

// ---------------------------------------------------------------------------
// Aggregation: one warp per edge. Reads a 256-float row of x (L2-resident),
// scales by 1/cnt, vector-atomic-adds into A[dst][r][:].
// ---------------------------------------------------------------------------
__global__ __launch_bounds__(256) void k_agg(
    const float* __restrict__ x,
    const void* __restrict__ ei,
    const void* __restrict__ et,
    const float* __restrict__ inv,
    float* __restrict__ A, int E)
{
    int w = (int)(((size_t)blockIdx.x * blockDim.x + threadIdx.x) >> 5);
    if (w >= E) return;
    int is64 = g_is64;
    int lane = threadIdx.x & 31;
    int src = load_idx(ei, w, is64);
    int dst = load_idx(ei, (long long)E + w, is64);
    int r   = load_idx(et, w, is64);
    float s = __ldg(&inv[dst * R_REL + r]);

    const float4* xs = (const float4*)(x + (size_t)src * 256);
    float* a = A + ((size_t)dst * R_REL + r) * 256;

    float4 v0 = xs[lane];
    float4 v1 = xs[lane + 32];

    asm volatile("red.global.add.v4.f32 [%0], {%1,%2,%3,%4};"
                 :: "l"(a + lane * 4),
                    "f"(v0.x * s), "f"(v0.y * s), "f"(v0.z * s), "f"(v0.w * s)
                 : "memory");
    asm volatile("red.global.add.v4.f32 [%0], {%1,%2,%3,%4};"
                 :: "l"(a + 128 + lane * 4),
                    "f"(v1.x * s), "f"(v1.y * s), "f"(v1.z * s), "f"(v1.w * s)
                 : "memory");
}

// ---------------------------------------------------------------------------
// Fused GEMM: out[n, outc] = relu?( [A | xr] @ [W ; root] + b )
// Tiling: 128x128x16, 256 threads, 8x8 per thread, fp32 FFMA.
// ---------------------------------------------------------------------------
__global__ __launch_bounds__(256) void k_gemm(
    const float* __restrict__ A,
    const float* __restrict__ xr,
    const float* __restrict__ W,
    const float* __restrict__ root,
    const float* __restrict__ bias,
    float* __restrict__ out,
    int n, int outc, int do_relu)
{
    const int BM = 128, BN = 128, BK = 16;
    __shared__ float As[BK][BM + 4];
    __shared__ float Bs[BK][BN];

    int tid = threadIdx.x;
    int m0 = blockIdx.x * BM;
    int n0 = blockIdx.y * BN;
    int tmBase = (tid >> 4) * 8;   // 0..120
    int tnBase = (tid & 15) * 8;   // 0..120

    float acc[8][8];
#pragma unroll
    for (int i = 0; i < 8; ++i)
#pragma unroll
        for (int j = 0; j < 8; ++j) acc[i][j] = 0.0f;

    const int KT = KTOT / BK;  // 144
    for (int kt = 0; kt < KT; ++kt) {
        int kbase = kt * BK;

        // --- A tile: 128 rows x 16 k, transposed into As[k][m] ---
#pragma unroll
        for (int j = 0; j < 2; ++j) {
            int idx = tid + j * 256;          // 0..511
            int row = idx >> 2;               // 0..127
            int c4  = idx & 3;                // 0..3 (float4 within 16 k)
            int node = m0 + row;
            if (node >= n) node = n - 1;
            int kg = kbase + c4 * 4;
            float4 v;
            if (kg < KA)
                v = *(const float4*)(A + (size_t)node * KA + kg);
            else
                v = *(const float4*)(xr + (size_t)node * 256 + (kg - KA));
            As[c4 * 4 + 0][row] = v.x;
            As[c4 * 4 + 1][row] = v.y;
            As[c4 * 4 + 2][row] = v.z;
            As[c4 * 4 + 3][row] = v.w;
        }

        // --- B tile: 16 k x 128 n ---
#pragma unroll
        for (int j = 0; j < 2; ++j) {
            int idx = tid + j * 256;          // 0..511
            int kr = idx >> 5;                // 0..15
            int c4 = idx & 31;                // 0..31
            int kg = kbase + kr;
            const float* src = (kg < KA)
                ? (W    + (size_t)kg * outc + n0 + c4 * 4)
                : (root + (size_t)(kg - KA) * outc + n0 + c4 * 4);
            *(float4*)&Bs[kr][c4 * 4] = *(const float4*)src;
        }

        __syncthreads();

#pragma unroll
        for (int k = 0; k < BK; ++k) {
            float a[8], bb[8];
            *(float4*)&a[0]  = *(const float4*)&As[k][tmBase];
            *(float4*)&a[4]  = *(const float4*)&As[k][tmBase + 4];
            *(float4*)&bb[0] = *(const float4*)&Bs[k][tnBase];
            *(float4*)&bb[4] = *(const float4*)&Bs[k][tnBase + 4];
#pragma unroll
            for (int i = 0; i < 8; ++i)
#pragma unroll
                for (int j = 0; j < 8; ++j)
                    acc[i][j] += a[i] * bb[j];
        }
        __syncthreads();
    }

    // --- epilogue: bias (+ relu) + vector store ---
    float bv[8];
    *(float4*)&bv[0] = *(const float4*)&bias[n0 + tnBase];
    *(float4*)&bv[4] = *(const float4*)&bias[n0 + tnBase + 4];

#pragma unroll
    for (int i = 0; i < 8; ++i) {
        int row = m0 + tmBase + i;
        if (row < n) {
            float o[8];
#pragma unroll
            for (int j = 0; j < 8; ++j) {
                float v = acc[i][j] + bv[j];
                o[j] = do_relu ? fmaxf(v, 0.0f) : v;
            }
            float* dst = out + (size_t)row * outc + n0 + tnBase;
            *(float4*)(dst)     = *(float4*)&o[0];
            *(float4*)(dst + 4) = *(float4*)&o[4];
        }
    }
}

// ---------------------------------------------------------------------------
extern "C" void kernel_launch(void* const* d_in, const int* in_sizes, int n_in,
                              void* d_out, int out_size)
{
    const float* x     = (const float*)d_in[0];
    const float* W1    = (const float*)d_in[1];  // [R, 256, 256] == [2048, 256]
    const float* root1 = (const float*)d_in[2];
    const float* b1    = (const float*)d_in[3];
    const float* W2    = (const float*)d_in[4];  // [R, 256, 128] == [2048, 128]
    const float* root2 = (const float*)d_in[5];
    const float* b2    = (const float*)d_in[6];
    const void*  ei    = d_in[7];                // [2, E] int32 or int64
    const void*  et    = d_in[8];                // [E]

    int E = in_sizes[8];
    int n = in_sizes[0] / C_IN;

    float *A, *h, *inv;
    cudaGetSymbolAddress((void**)&A,   g_A);
    cudaGetSymbolAddress((void**)&h,   g_h);
    cudaGetSymbolAddress((void**)&inv, g_inv);

    size_t abytes = sizeof(float) * (size_t)R_REL * n * 256;

    // dtype detection (must precede any index consumer)
    k_detect<<<1, 32>>>((const unsigned*)ei, 2 * E);

    // counts (shared across both layers)
    cudaMemsetAsync(inv, 0, sizeof(float) * (size_t)n * R_REL, 0);
    k_count<<<(E + 255) / 256, 256>>>(ei, et, inv, E);
    k_inv<<<(n * R_REL + 255) / 256, 256>>>(inv, n * R_REL);

    // ---- layer 1 ----
    cudaMemsetAsync(A, 0, abytes, 0);
    k_agg<<<(E + 7) / 8, 256>>>(x, ei, et, inv, A, E);
    k_gemm<<<dim3((n + 127) / 128, C_HID / 128), 256>>>(A, x, W1, root1, b1, h, n, C_HID, 1);

    // ---- layer 2 ----
    cudaMemsetAsync(A, 0, abytes, 0);
    k_agg<<<(E + 7) / 8, 256>>>(h, ei, et, inv, A, E);
    k_gemm<<<dim3((n + 127) / 128, C_OUT / 128), 256>>>(A, h, W2, root2, b2, (float*)d_out, n, C_OUT, 0);
}

// round 3
// speedup vs baseline: 1.0278x; 1.0278x over previous
#include <cuda_runtime.h>

#define N_NODES 20000
#define R_REL   8
#define C_IN    256
#define C_HID   256
#define C_OUT   128
#define KA      (R_REL * 256)   // 2048 aggregated-feature K
#define KTOT    (KA + 256)      // 2304 total K (agg + root/self)

// Scratch (static device globals — no runtime allocation).
__device__ float g_A[(size_t)R_REL * N_NODES * 256];  // [N][R][256]
__device__ float g_h[(size_t)N_NODES * C_HID];        // layer-1 activations
__device__ float g_inv[N_NODES * R_REL];              // counts -> 1/max(cnt,1)
__device__ int   g_is64;                              // edge index dtype flag

// ---------------------------------------------------------------------------
// Index dtype detector (int64 vs int32 edge buffers).
// ---------------------------------------------------------------------------
__global__ void k_detect(const unsigned* __restrict__ ei_words, int nwords) {
    if (threadIdx.x == 0 && blockIdx.x == 0) {
        int is64 = 1;
        int lim = nwords < 256 ? nwords : 256;
        for (int i = 1; i < lim; i += 2)
            if (ei_words[i] != 0u) { is64 = 0; break; }
        g_is64 = is64;
    }
}

__device__ __forceinline__ int load_idx(const void* p, long long i, int is64) {
    return is64 ? (int)((const long long*)p)[i] : ((const int*)p)[i];
}

// ---------------------------------------------------------------------------
// Per-(dst, rel) edge counts
// ---------------------------------------------------------------------------
__global__ void k_count(const void* __restrict__ ei,
                        const void* __restrict__ et,
                        float* __restrict__ cnt, int E) {
    int e = blockIdx.x * blockDim.x + threadIdx.x;
    if (e >= E) return;
    int is64 = g_is64;
    int dst = load_idx(ei, (long long)E + e, is64);
    int r   = load_idx(et, e, is64);
    atomicAdd(&cnt[dst * R_REL + r], 1.0f);
}

__global__ void k_inv(float* __restrict__ cnt, int n) {
    int i = blockIdx.x * blockDim.x + threadIdx.x;
    if (i < n) cnt[i] = 1.0f / fmaxf(cnt[i], 1.0f);
}

// ---------------------------------------------------------------------------
// Aggregation: one warp per edge, vector red.global into A[dst][r][:].
// ---------------------------------------------------------------------------
__global__ __launch_bounds__(256) void k_agg(
    const float* __restrict__ x,
    const void* __restrict__ ei,
    const void* __restrict__ et,
    const float* __restrict__ inv,
    float* __restrict__ A, int E)
{
    int w = (int)(((size_t)blockIdx.x * blockDim.x + threadIdx.x) >> 5);
    if (w >= E) return;
    int is64 = g_is64;
    int lane = threadIdx.x & 31;
    int src = load_idx(ei, w, is64);
    int dst = load_idx(ei, (long long)E + w, is64);
    int r   = load_idx(et, w, is64);
    float s = __ldg(&inv[dst * R_REL + r]);

    const float4* xs = (const float4*)(x + (size_t)src * 256);
    float* a = A + ((size_t)dst * R_REL + r) * 256;

    float4 v0 = xs[lane];
    float4 v1 = xs[lane + 32];

    asm volatile("red.global.add.v4.f32 [%0], {%1,%2,%3,%4};"
                 :: "l"(a + lane * 4),
                    "f"(v0.x * s), "f"(v0.y * s), "f"(v0.z * s), "f"(v0.w * s)
                 : "memory");
    asm volatile("red.global.add.v4.f32 [%0], {%1,%2,%3,%4};"
                 :: "l"(a + 128 + lane * 4),
                    "f"(v1.x * s), "f"(v1.y * s), "f"(v1.z * s), "f"(v1.w * s)
                 : "memory");
}

// ---------------------------------------------------------------------------
// Fused GEMM with packed fp32 (fma.rn.f32x2, Blackwell FFMA2):
//   out[n, outc] = relu?( [A | xr] @ [W ; root] + b )
// Tiling: 128x128x16, 256 threads, 8x8 per thread (stored as 8x4 f32x2 pairs).
// ---------------------------------------------------------------------------
__global__ __launch_bounds__(256) void k_gemm(
    const float* __restrict__ A,
    const float* __restrict__ xr,
    const float* __restrict__ W,
    const float* __restrict__ root,
    const float* __restrict__ bias,
    float* __restrict__ out,
    int n, int outc, int do_relu)
{
    const int BM = 128, BN = 128, BK = 16;
    __shared__ float As[BK][BM + 4];
    __shared__ float Bs[BK][BN];

    int tid = threadIdx.x;
    int m0 = blockIdx.x * BM;
    int n0 = blockIdx.y * BN;
    int tmBase = (tid >> 4) * 8;   // 0..120
    int tnBase = (tid & 15) * 8;   // 0..120

    // 8 rows x 4 packed column-pairs of fp32x2 accumulators (== 8x8 scalars)
    unsigned long long acc[8][4];
#pragma unroll
    for (int i = 0; i < 8; ++i)
#pragma unroll
        for (int j = 0; j < 4; ++j) acc[i][j] = 0ULL;

    const int KT = KTOT / BK;  // 144
    for (int kt = 0; kt < KT; ++kt) {
        int kbase = kt * BK;

        // --- A tile: 128 rows x 16 k, transposed into As[k][m] ---
#pragma unroll
        for (int j = 0; j < 2; ++j) {
            int idx = tid + j * 256;          // 0..511
            int row = idx >> 2;               // 0..127
            int c4  = idx & 3;                // float4 within 16 k
            int node = m0 + row;
            if (node >= n) node = n - 1;
            int kg = kbase + c4 * 4;
            float4 v;
            if (kg < KA)
                v = *(const float4*)(A + (size_t)node * KA + kg);
            else
                v = *(const float4*)(xr + (size_t)node * 256 + (kg - KA));
            As[c4 * 4 + 0][row] = v.x;
            As[c4 * 4 + 1][row] = v.y;
            As[c4 * 4 + 2][row] = v.z;
            As[c4 * 4 + 3][row] = v.w;
        }

        // --- B tile: 16 k x 128 n ---
#pragma unroll
        for (int j = 0; j < 2; ++j) {
            int idx = tid + j * 256;          // 0..511
            int kr = idx >> 5;                // 0..15
            int c4 = idx & 31;                // 0..31
            int kg = kbase + kr;
            const float* src = (kg < KA)
                ? (W    + (size_t)kg * outc + n0 + c4 * 4)
                : (root + (size_t)(kg - KA) * outc + n0 + c4 * 4);
            *(float4*)&Bs[kr][c4 * 4] = *(const float4*)src;
        }

        __syncthreads();

#pragma unroll
        for (int k = 0; k < BK; ++k) {
            float a[8];
            *(float4*)&a[0] = *(const float4*)&As[k][tmBase];
            *(float4*)&a[4] = *(const float4*)&As[k][tmBase + 4];

            // B column pairs as packed f32x2 (adjacent floats in Bs)
            unsigned long long bp[4];
            const ulonglong2* bsrc = (const ulonglong2*)&Bs[k][tnBase];
            ulonglong2 t0 = bsrc[0];
            ulonglong2 t1 = bsrc[1];
            bp[0] = t0.x; bp[1] = t0.y; bp[2] = t1.x; bp[3] = t1.y;

#pragma unroll
            for (int i = 0; i < 8; ++i) {
                unsigned long long aa;
                asm("mov.b64 %0, {%1, %1};" : "=l"(aa) : "f"(a[i]));
#pragma unroll
                for (int j = 0; j < 4; ++j)
                    asm("fma.rn.f32x2 %0, %1, %2, %0;"
                        : "+l"(acc[i][j]) : "l"(aa), "l"(bp[j]));
            }
        }
        __syncthreads();
    }

    // --- epilogue: unpack, bias (+ relu), vector store ---
    float bv[8];
    *(float4*)&bv[0] = *(const float4*)&bias[n0 + tnBase];
    *(float4*)&bv[4] = *(const float4*)&bias[n0 + tnBase + 4];

#pragma unroll
    for (int i = 0; i < 8; ++i) {
        int row = m0 + tmBase + i;
        if (row < n) {
            float o[8];
#pragma unroll
            for (int j = 0; j < 4; ++j) {
                float lo, hi;
                asm("mov.b64 {%0, %1}, %2;" : "=f"(lo), "=f"(hi) : "l"(acc[i][j]));
                float v0 = lo + bv[2 * j];
                float v1 = hi + bv[2 * j + 1];
                o[2 * j]     = do_relu ? fmaxf(v0, 0.0f) : v0;
                o[2 * j + 1] = do_relu ? fmaxf(v1, 0.0f) : v1;
            }
            float* dst = out + (size_t)row * outc + n0 + tnBase;
            *(float4*)(dst)     = *(float4*)&o[0];
            *(float4*)(dst + 4) = *(float4*)&o[4];
        }
    }
}

// ---------------------------------------------------------------------------
extern "C" void kernel_launch(void* const* d_in, const int* in_sizes, int n_in,
                              void* d_out, int out_size)
{
    const float* x     = (const float*)d_in[0];
    const float* W1    = (const float*)d_in[1];  // [R, 256, 256] == [2048, 256]
    const float* root1 = (const float*)d_in[2];
    const float* b1    = (const float*)d_in[3];
    const float* W2    = (const float*)d_in[4];  // [R, 256, 128] == [2048, 128]
    const float* root2 = (const float*)d_in[5];
    const float* b2    = (const float*)d_in[6];
    const void*  ei    = d_in[7];                // [2, E] int32 or int64
    const void*  et    = d_in[8];                // [E]

    int E = in_sizes[8];
    int n = in_sizes[0] / C_IN;

    float *A, *h, *inv;
    cudaGetSymbolAddress((void**)&A,   g_A);
    cudaGetSymbolAddress((void**)&h,   g_h);
    cudaGetSymbolAddress((void**)&inv, g_inv);

    size_t abytes = sizeof(float) * (size_t)R_REL * n * 256;

    // dtype detection (must precede any index consumer)
    k_detect<<<1, 32>>>((const unsigned*)ei, 2 * E);

    // counts (shared across both layers)
    cudaMemsetAsync(inv, 0, sizeof(float) * (size_t)n * R_REL, 0);
    k_count<<<(E + 255) / 256, 256>>>(ei, et, inv, E);
    k_inv<<<(n * R_REL + 255) / 256, 256>>>(inv, n * R_REL);

    // ---- layer 1 ----
    cudaMemsetAsync(A, 0, abytes, 0);
    k_agg<<<(E + 7) / 8, 256>>>(x, ei, et, inv, A, E);
    k_gemm<<<dim3((n + 127) / 128, C_HID / 128), 256>>>(A, x, W1, root1, b1, h, n, C_HID, 1);

    // ---- layer 2 ----
    cudaMemsetAsync(A, 0, abytes, 0);
    k_agg<<<(E + 7) / 8, 256>>>(h, ei, et, inv, A, E);
    k_gemm<<<dim3((n + 127) / 128, C_OUT / 128), 256>>>(A, h, W2, root2, b2, (float*)d_out, n, C_OUT, 0);
}

// round 5
// speedup vs baseline: 1.6291x; 1.5849x over previous
#include <cuda_runtime.h>
#include <cuda_bf16.h>
#include <cstdint>

#define N_NODES 20000
#define R_REL   8
#define KA      2048            // aggregated K (R*256)
#define KTOT    2304            // + 256 self/root
#define BK      32
#define LDT     40              // padded SMEM stride (bf16 elems)

// ---------------- scratch (static device globals) ----------------
__device__ float g_A[(size_t)N_NODES * KA];
__device__ float g_h[(size_t)N_NODES * 256];
__device__ float g_inv[N_NODES * R_REL];
__device__ int   g_is64;
__device__ __nv_bfloat16 g_Wh1[256 * KTOT];
__device__ __nv_bfloat16 g_Wl1[256 * KTOT];
__device__ __nv_bfloat16 g_Wh2[128 * KTOT];
__device__ __nv_bfloat16 g_Wl2[128 * KTOT];

// ---------------- graph prep kernels ----------------
__global__ void k_zero_detect(float4* A, float4* inv, int a4, int i4,
                              const unsigned* __restrict__ ei_words, int nwords) {
    int t = blockIdx.x * blockDim.x + threadIdx.x;
    if (t == 0) {
        int is64 = 1;
        int lim = nwords < 256 ? nwords : 256;
        for (int i = 1; i < lim; i += 2)
            if (ei_words[i] != 0u) { is64 = 0; break; }
        g_is64 = is64;
    }
    float4 z = make_float4(0.f, 0.f, 0.f, 0.f);
    int stride = gridDim.x * blockDim.x;
    for (int i = t; i < a4; i += stride) A[i] = z;
    for (int i = t; i < i4; i += stride) inv[i] = z;
}

__device__ __forceinline__ int load_idx(const void* p, long long i, int is64) {
    return is64 ? (int)((const long long*)p)[i] : ((const int*)p)[i];
}

__global__ void k_count(const void* __restrict__ ei, const void* __restrict__ et,
                        float* __restrict__ cnt, int E) {
    int e = blockIdx.x * blockDim.x + threadIdx.x;
    if (e >= E) return;
    int is64 = g_is64;
    int dst = load_idx(ei, (long long)E + e, is64);
    int r   = load_idx(et, e, is64);
    atomicAdd(&cnt[dst * R_REL + r], 1.0f);
}

__global__ void k_inv(float* __restrict__ cnt, int n) {
    int i = blockIdx.x * blockDim.x + threadIdx.x;
    if (i < n) cnt[i] = 1.0f / fmaxf(cnt[i], 1.0f);
}

// Weight precompute: Wt[n][k] bf16 hi/lo transposed from [k][n] fp32 (W ; root).
__global__ void k_wconv(const float* __restrict__ W1, const float* __restrict__ r1,
                        const float* __restrict__ W2, const float* __restrict__ r2) {
    int idx = blockIdx.x * blockDim.x + threadIdx.x;
    const int L1 = 256 * KTOT;
    const int L2 = 128 * KTOT;
    if (idx < L1) {
        int nrow = idx / KTOT, k = idx % KTOT;
        float v = (k < KA) ? W1[(size_t)k * 256 + nrow] : r1[(size_t)(k - KA) * 256 + nrow];
        __nv_bfloat16 h = __float2bfloat16_rn(v);
        g_Wh1[idx] = h;
        g_Wl1[idx] = __float2bfloat16_rn(v - __bfloat162float(h));
    } else if (idx < L1 + L2) {
        int i2 = idx - L1;
        int nrow = i2 / KTOT, k = i2 % KTOT;
        float v = (k < KA) ? W2[(size_t)k * 128 + nrow] : r2[(size_t)(k - KA) * 128 + nrow];
        __nv_bfloat16 h = __float2bfloat16_rn(v);
        g_Wh2[i2] = h;
        g_Wl2[i2] = __float2bfloat16_rn(v - __bfloat162float(h));
    }
}

// ---------------- aggregation (DRAM-bound, unchanged) ----------------
__global__ __launch_bounds__(256) void k_agg(
    const float* __restrict__ x,
    const void* __restrict__ ei, const void* __restrict__ et,
    const float* __restrict__ inv, float* __restrict__ A, int E)
{
    int w = (int)(((size_t)blockIdx.x * blockDim.x + threadIdx.x) >> 5);
    if (w >= E) return;
    int is64 = g_is64;
    int lane = threadIdx.x & 31;
    int src = load_idx(ei, w, is64);
    int dst = load_idx(ei, (long long)E + w, is64);
    int r   = load_idx(et, w, is64);
    float s = __ldg(&inv[dst * R_REL + r]);

    const float4* xs = (const float4*)(x + (size_t)src * 256);
    float* a = A + ((size_t)dst * R_REL + r) * 256;

    float4 v0 = xs[lane];
    float4 v1 = xs[lane + 32];
    asm volatile("red.global.add.v4.f32 [%0], {%1,%2,%3,%4};"
                 :: "l"(a + lane * 4),
                    "f"(v0.x * s), "f"(v0.y * s), "f"(v0.z * s), "f"(v0.w * s) : "memory");
    asm volatile("red.global.add.v4.f32 [%0], {%1,%2,%3,%4};"
                 :: "l"(a + 128 + lane * 4),
                    "f"(v1.x * s), "f"(v1.y * s), "f"(v1.z * s), "f"(v1.w * s) : "memory");
}

// ---------------- mma.sync bf16-split GEMM ----------------
// out[n, outc] = relu?( [Aagg | xr] @ Wt^T + b ),  Wt: [outc][KTOT] bf16 hi/lo.
// CTA 128x128, 8 warps (4m x 2n), warp tile 32x64 = 2x8 m16n8k16 frags.
#define MMA_BF16(C, A0, A1, A2, A3, B0, B1)                                   \
    asm volatile(                                                             \
        "mma.sync.aligned.m16n8k16.row.col.f32.bf16.bf16.f32 "                \
        "{%0,%1,%2,%3}, {%4,%5,%6,%7}, {%8,%9}, {%0,%1,%2,%3};"               \
        : "+f"(C[0]), "+f"(C[1]), "+f"(C[2]), "+f"(C[3])                      \
        : "r"(A0), "r"(A1), "r"(A2), "r"(A3), "r"(B0), "r"(B1))

__global__ __launch_bounds__(256) void k_gemm_mma(
    const float* __restrict__ Aagg, const float* __restrict__ xr,
    const __nv_bfloat16* __restrict__ Wh, const __nv_bfloat16* __restrict__ Wl,
    const float* __restrict__ bias, float* __restrict__ out,
    int n, int outc, int do_relu)
{
    __shared__ __nv_bfloat16 sAh[128 * LDT];
    __shared__ __nv_bfloat16 sAl[128 * LDT];
    __shared__ __nv_bfloat16 sBh[128 * LDT];
    __shared__ __nv_bfloat16 sBl[128 * LDT];

    const int tid  = threadIdx.x;
    const int wid  = tid >> 5;
    const int lane = tid & 31;
    const int g    = lane >> 2;      // group id (0..7)
    const int t    = lane & 3;       // thread in group
    const int m0   = blockIdx.x * 128;
    const int n0   = blockIdx.y * 128;
    const int warpM = (wid & 3) * 32;
    const int warpN = (wid >> 2) * 64;

    float acc[2][8][4];
#pragma unroll
    for (int mi = 0; mi < 2; ++mi)
#pragma unroll
        for (int ni = 0; ni < 8; ++ni)
#pragma unroll
            for (int c = 0; c < 4; ++c) acc[mi][ni][c] = 0.0f;

    // staging maps
    const int arow  = tid >> 1;
    const int akoff = (tid & 1) * 16;
    int anode = m0 + arow; if (anode >= n) anode = n - 1;
    const int brow  = tid >> 1;
    const int bkoff = (tid & 1) * 16;

    for (int kt = 0; kt < KTOT / BK; ++kt) {
        const int kbase = kt * BK;

        // --- stage A (fp32 -> bf16 hi/lo) ---
        const float* abase = (kbase < KA)
            ? (Aagg + (size_t)anode * KA + kbase)
            : (xr   + (size_t)anode * 256 + (kbase - KA));
#pragma unroll
        for (int j = 0; j < 4; ++j) {
            float4 v = *(const float4*)(abase + akoff + 4 * j);
            __nv_bfloat162 h01 = __floats2bfloat162_rn(v.x, v.y);
            __nv_bfloat162 h23 = __floats2bfloat162_rn(v.z, v.w);
            __nv_bfloat162 l01 = __floats2bfloat162_rn(v.x - __low2float(h01),
                                                       v.y - __high2float(h01));
            __nv_bfloat162 l23 = __floats2bfloat162_rn(v.z - __low2float(h23),
                                                       v.w - __high2float(h23));
            int off = arow * LDT + akoff + 4 * j;
            uint2 hw, lw;
            hw.x = *(unsigned*)&h01; hw.y = *(unsigned*)&h23;
            lw.x = *(unsigned*)&l01; lw.y = *(unsigned*)&l23;
            *(uint2*)&sAh[off] = hw;
            *(uint2*)&sAl[off] = lw;
        }

        // --- stage B (bf16 copy) ---
        {
            const __nv_bfloat16* bh = Wh + (size_t)(n0 + brow) * KTOT + kbase + bkoff;
            const __nv_bfloat16* bl = Wl + (size_t)(n0 + brow) * KTOT + kbase + bkoff;
            int off = brow * LDT + bkoff;
            *(uint4*)&sBh[off]     = *(const uint4*)bh;
            *(uint4*)&sBh[off + 8] = *(const uint4*)(bh + 8);
            *(uint4*)&sBl[off]     = *(const uint4*)bl;
            *(uint4*)&sBl[off + 8] = *(const uint4*)(bl + 8);
        }
        __syncthreads();

        // --- compute: 2 k16 steps ---
#pragma unroll
        for (int ks = 0; ks < 2; ++ks) {
            const int kk = ks * 16;
            uint32_t ah[2][4], al[2][4];
#pragma unroll
            for (int mi = 0; mi < 2; ++mi) {
                int r = warpM + mi * 16 + g;
                int o0 = r * LDT + kk + 2 * t;
                int o1 = (r + 8) * LDT + kk + 2 * t;
                ah[mi][0] = *(const uint32_t*)&sAh[o0];
                ah[mi][1] = *(const uint32_t*)&sAh[o1];
                ah[mi][2] = *(const uint32_t*)&sAh[o0 + 8];
                ah[mi][3] = *(const uint32_t*)&sAh[o1 + 8];
                al[mi][0] = *(const uint32_t*)&sAl[o0];
                al[mi][1] = *(const uint32_t*)&sAl[o1];
                al[mi][2] = *(const uint32_t*)&sAl[o0 + 8];
                al[mi][3] = *(const uint32_t*)&sAl[o1 + 8];
            }
            uint32_t bh[8][2], bl[8][2];
#pragma unroll
            for (int ni = 0; ni < 8; ++ni) {
                int c = warpN + ni * 8 + g;
                int o = c * LDT + kk + 2 * t;
                bh[ni][0] = *(const uint32_t*)&sBh[o];
                bh[ni][1] = *(const uint32_t*)&sBh[o + 8];
                bl[ni][0] = *(const uint32_t*)&sBl[o];
                bl[ni][1] = *(const uint32_t*)&sBl[o + 8];
            }
#pragma unroll
            for (int mi = 0; mi < 2; ++mi)
#pragma unroll
                for (int ni = 0; ni < 8; ++ni) {
                    MMA_BF16(acc[mi][ni], ah[mi][0], ah[mi][1], ah[mi][2], ah[mi][3],
                             bh[ni][0], bh[ni][1]);
                    MMA_BF16(acc[mi][ni], al[mi][0], al[mi][1], al[mi][2], al[mi][3],
                             bh[ni][0], bh[ni][1]);
                    MMA_BF16(acc[mi][ni], ah[mi][0], ah[mi][1], ah[mi][2], ah[mi][3],
                             bl[ni][0], bl[ni][1]);
                }
        }
        __syncthreads();
    }

    // --- epilogue ---
#pragma unroll
    for (int mi = 0; mi < 2; ++mi) {
        int r0 = m0 + warpM + mi * 16 + g;
#pragma unroll
        for (int ni = 0; ni < 8; ++ni) {
            int c = n0 + warpN + ni * 8 + 2 * t;
            float b0 = bias[c], b1 = bias[c + 1];
            float v0 = acc[mi][ni][0] + b0;
            float v1 = acc[mi][ni][1] + b1;
            float v2 = acc[mi][ni][2] + b0;
            float v3 = acc[mi][ni][3] + b1;
            if (do_relu) {
                v0 = fmaxf(v0, 0.f); v1 = fmaxf(v1, 0.f);
                v2 = fmaxf(v2, 0.f); v3 = fmaxf(v3, 0.f);
            }
            if (r0 < n)     *(float2*)(out + (size_t)r0 * outc + c)       = make_float2(v0, v1);
            if (r0 + 8 < n) *(float2*)(out + (size_t)(r0 + 8) * outc + c) = make_float2(v2, v3);
        }
    }
}

// ---------------------------------------------------------------------------
extern "C" void kernel_launch(void* const* d_in, const int* in_sizes, int n_in,
                              void* d_out, int out_size)
{
    const float* x     = (const float*)d_in[0];
    const float* W1    = (const float*)d_in[1];
    const float* root1 = (const float*)d_in[2];
    const float* b1    = (const float*)d_in[3];
    const float* W2    = (const float*)d_in[4];
    const float* root2 = (const float*)d_in[5];
    const float* b2    = (const float*)d_in[6];
    const void*  ei    = d_in[7];
    const void*  et    = d_in[8];

    int E = in_sizes[8];
    int n = in_sizes[0] / 256;

    float *A, *h, *inv;
    cudaGetSymbolAddress((void**)&A,   g_A);
    cudaGetSymbolAddress((void**)&h,   g_h);
    cudaGetSymbolAddress((void**)&inv, g_inv);
    __nv_bfloat16 *Wh1, *Wl1, *Wh2, *Wl2;
    cudaGetSymbolAddress((void**)&Wh1, g_Wh1);
    cudaGetSymbolAddress((void**)&Wl1, g_Wl1);
    cudaGetSymbolAddress((void**)&Wh2, g_Wh2);
    cudaGetSymbolAddress((void**)&Wl2, g_Wl2);

    size_t abytes = sizeof(float) * (size_t)n * KA;
    int a4 = n * KA / 4, i4 = n * R_REL / 4;
    dim3 g1((n + 127) / 128, 2);   // outc = 256
    dim3 g2((n + 127) / 128, 1);   // outc = 128

    // Launch order keeps k_gemm_mma (layer 1) as the 6th launch (ncu -s 5 -c 1).
    k_zero_detect<<<40000, 256>>>((float4*)A, (float4*)inv, a4, i4, (const unsigned*)ei, 2 * E);
    k_wconv<<<(384 * KTOT + 255) / 256, 256>>>(W1, root1, W2, root2);
    k_count<<<(E + 255) / 256, 256>>>(ei, et, inv, E);
    k_inv<<<(n * R_REL + 255) / 256, 256>>>(inv, n * R_REL);

    // ---- layer 1 ----
    k_agg<<<(E + 7) / 8, 256>>>(x, ei, et, inv, A, E);
    k_gemm_mma<<<g1, 256>>>(A, x, Wh1, Wl1, b1, h, n, 256, 1);

    // ---- layer 2 ----
    cudaMemsetAsync(A, 0, abytes, 0);
    k_agg<<<(E + 7) / 8, 256>>>(h, ei, et, inv, A, E);
    k_gemm_mma<<<g2, 256>>>(A, h, Wh2, Wl2, b2, (float*)d_out, n, 128, 0);
}

// round 6
// speedup vs baseline: 2.3123x; 1.4194x over previous
#include <cuda_runtime.h>
#include <cuda_bf16.h>
#include <cstdint>

#define N_NODES 20000
#define R_REL   8
#define KA      2048
#define KTOT    2304
#define BK      32
#define LDT     40
#define NSEG_MX (N_NODES * R_REL)
#define E_MAX   650000

// ---------------- static device scratch ----------------
__device__ __nv_bfloat16 g_Ah[(size_t)N_NODES * KA];
__device__ __nv_bfloat16 g_Al[(size_t)N_NODES * KA];
__device__ __nv_bfloat16 g_X1h[(size_t)N_NODES * 256];
__device__ __nv_bfloat16 g_X1l[(size_t)N_NODES * 256];
__device__ __nv_bfloat16 g_X2h[(size_t)N_NODES * 256];
__device__ __nv_bfloat16 g_X2l[(size_t)N_NODES * 256];
__device__ float g_h[(size_t)N_NODES * 256];
__device__ int   g_cnt[NSEG_MX];
__device__ int   g_off[NSEG_MX + 1];
__device__ int   g_cur[NSEG_MX];
__device__ int   g_part[(NSEG_MX + 255) / 256];
__device__ int   g_sorted[E_MAX];
__device__ int   g_is64;
__device__ __nv_bfloat16 g_Wh1[256 * KTOT];
__device__ __nv_bfloat16 g_Wl1[256 * KTOT];
__device__ __nv_bfloat16 g_Wh2[128 * KTOT];
__device__ __nv_bfloat16 g_Wl2[128 * KTOT];

__device__ __forceinline__ int load_idx(const void* p, long long i, int is64) {
    return is64 ? (int)((const long long*)p)[i] : ((const int*)p)[i];
}

// ---------------- prep kernels ----------------
__global__ void k_detect_zero(const unsigned* __restrict__ ei_words, int nwords, int nseg) {
    int i = blockIdx.x * blockDim.x + threadIdx.x;
    if (i == 0) {
        int is64 = 1;
        int lim = nwords < 256 ? nwords : 256;
        for (int j = 1; j < lim; j += 2)
            if (ei_words[j] != 0u) { is64 = 0; break; }
        g_is64 = is64;
    }
    if (i < nseg) g_cnt[i] = 0;
}

__global__ void k_count(const void* __restrict__ ei, const void* __restrict__ et, int E) {
    int e = blockIdx.x * blockDim.x + threadIdx.x;
    if (e >= E) return;
    int is64 = g_is64;
    int dst = load_idx(ei, (long long)E + e, is64);
    int r   = load_idx(et, e, is64);
    atomicAdd(&g_cnt[dst * R_REL + r], 1);
}

__global__ void k_scan1(int nseg) {
    __shared__ int sh[256];
    int b = blockIdx.x, t = threadIdx.x, i = b * 256 + t;
    int v = (i < nseg) ? g_cnt[i] : 0;
    sh[t] = v; __syncthreads();
#pragma unroll
    for (int d = 1; d < 256; d <<= 1) {
        int add = (t >= d) ? sh[t - d] : 0;
        __syncthreads();
        sh[t] += add;
        __syncthreads();
    }
    if (i < nseg) g_off[i + 1] = sh[t];
    if (t == 255) g_part[b] = sh[255];
}

__global__ void k_scan2(int nseg) {
    __shared__ int sh[256];
    int b = blockIdx.x, t = threadIdx.x, i = b * 256 + t;
    int s = 0;
    for (int j = t; j < b; j += 256) s += g_part[j];
    sh[t] = s; __syncthreads();
#pragma unroll
    for (int d = 128; d > 0; d >>= 1) { if (t < d) sh[t] += sh[t + d]; __syncthreads(); }
    int base = sh[0];
    int selfv = (i < nseg) ? g_off[i + 1] : 0;
    int prev  = (t > 0 && i < nseg) ? g_off[i] : 0;
    __syncthreads();
    if (i < nseg) {
        g_off[i + 1] = selfv + base;
        g_cur[i] = base + prev;
    }
    if (b == 0 && t == 0) g_off[0] = 0;
}

__global__ void k_scatter(const void* __restrict__ ei, const void* __restrict__ et, int E) {
    int e = blockIdx.x * blockDim.x + threadIdx.x;
    if (e >= E) return;
    int is64 = g_is64;
    int src = load_idx(ei, e, is64);
    int dst = load_idx(ei, (long long)E + e, is64);
    int r   = load_idx(et, e, is64);
    int pos = atomicAdd(&g_cur[dst * R_REL + r], 1);
    g_sorted[pos] = src;
}

// ---------------- CSR aggregation: warp per (dst,rel) segment ----------------
__global__ __launch_bounds__(256) void k_agg_csr(
    const float* __restrict__ x,
    __nv_bfloat16* __restrict__ Ah, __nv_bfloat16* __restrict__ Al, int nseg)
{
    int w = (int)(((size_t)blockIdx.x * blockDim.x + threadIdx.x) >> 5);
    if (w >= nseg) return;
    int lane = threadIdx.x & 31;
    int beg = g_off[w], end = g_off[w + 1];
    int cnt = end - beg;

    float4 a0 = make_float4(0.f, 0.f, 0.f, 0.f);
    float4 a1 = make_float4(0.f, 0.f, 0.f, 0.f);

    for (int base = beg; base < end; base += 32) {
        int m = end - base; if (m > 32) m = 32;
        int myE = (lane < m) ? g_sorted[base + lane] : 0;
        for (int j = 0; j < m; ++j) {
            int src = __shfl_sync(0xffffffffu, myE, j);
            const float4* xs = (const float4*)(x + (size_t)src * 256 + lane * 8);
            float4 v0 = xs[0], v1 = xs[1];
            a0.x += v0.x; a0.y += v0.y; a0.z += v0.z; a0.w += v0.w;
            a1.x += v1.x; a1.y += v1.y; a1.z += v1.z; a1.w += v1.w;
        }
    }
    float s = cnt > 0 ? 1.0f / (float)cnt : 0.0f;
    a0.x *= s; a0.y *= s; a0.z *= s; a0.w *= s;
    a1.x *= s; a1.y *= s; a1.z *= s; a1.w *= s;

    __nv_bfloat162 h01 = __floats2bfloat162_rn(a0.x, a0.y);
    __nv_bfloat162 h23 = __floats2bfloat162_rn(a0.z, a0.w);
    __nv_bfloat162 h45 = __floats2bfloat162_rn(a1.x, a1.y);
    __nv_bfloat162 h67 = __floats2bfloat162_rn(a1.z, a1.w);
    __nv_bfloat162 l01 = __floats2bfloat162_rn(a0.x - __low2float(h01), a0.y - __high2float(h01));
    __nv_bfloat162 l23 = __floats2bfloat162_rn(a0.z - __low2float(h23), a0.w - __high2float(h23));
    __nv_bfloat162 l45 = __floats2bfloat162_rn(a1.x - __low2float(h45), a1.y - __high2float(h45));
    __nv_bfloat162 l67 = __floats2bfloat162_rn(a1.z - __low2float(h67), a1.w - __high2float(h67));

    size_t o = (size_t)w * 256 + lane * 8;
    uint4 hv, lv;
    hv.x = *(unsigned*)&h01; hv.y = *(unsigned*)&h23; hv.z = *(unsigned*)&h45; hv.w = *(unsigned*)&h67;
    lv.x = *(unsigned*)&l01; lv.y = *(unsigned*)&l23; lv.z = *(unsigned*)&l45; lv.w = *(unsigned*)&l67;
    *(uint4*)(Ah + o) = hv;
    *(uint4*)(Al + o) = lv;
}

// ---------------- weight / input conversion ----------------
__global__ void k_wconv(const float* __restrict__ W1, const float* __restrict__ r1,
                        const float* __restrict__ W2, const float* __restrict__ r2) {
    int idx = blockIdx.x * blockDim.x + threadIdx.x;
    const int L1 = 256 * KTOT, L2 = 128 * KTOT;
    if (idx < L1) {
        int nrow = idx / KTOT, k = idx % KTOT;
        float v = (k < KA) ? W1[(size_t)k * 256 + nrow] : r1[(size_t)(k - KA) * 256 + nrow];
        __nv_bfloat16 h = __float2bfloat16_rn(v);
        g_Wh1[idx] = h;
        g_Wl1[idx] = __float2bfloat16_rn(v - __bfloat162float(h));
    } else if (idx < L1 + L2) {
        int i2 = idx - L1;
        int nrow = i2 / KTOT, k = i2 % KTOT;
        float v = (k < KA) ? W2[(size_t)k * 128 + nrow] : r2[(size_t)(k - KA) * 128 + nrow];
        __nv_bfloat16 h = __float2bfloat16_rn(v);
        g_Wh2[i2] = h;
        g_Wl2[i2] = __float2bfloat16_rn(v - __bfloat162float(h));
    }
}

__global__ void k_xconv(const float* __restrict__ x, int total) {
    int idx = blockIdx.x * blockDim.x + threadIdx.x;
    if (idx >= total) return;
    float v = x[idx];
    __nv_bfloat16 h = __float2bfloat16_rn(v);
    g_X1h[idx] = h;
    g_X1l[idx] = __float2bfloat16_rn(v - __bfloat162float(h));
}

// ---------------- pipelined mma.sync bf16-split GEMM ----------------
#define MMA_BF16(C, A0, A1, A2, A3, B0, B1)                                   \
    asm volatile(                                                             \
        "mma.sync.aligned.m16n8k16.row.col.f32.bf16.bf16.f32 "                \
        "{%0,%1,%2,%3}, {%4,%5,%6,%7}, {%8,%9}, {%0,%1,%2,%3};"               \
        : "+f"(C[0]), "+f"(C[1]), "+f"(C[2]), "+f"(C[3])                      \
        : "r"(A0), "r"(A1), "r"(A2), "r"(A3), "r"(B0), "r"(B1))

__device__ __forceinline__ uint32_t smem_u32(const void* p) {
    uint32_t a;
    asm("{ .reg .u64 t; cvta.to.shared.u64 t, %1; cvt.u32.u64 %0, t; }" : "=r"(a) : "l"(p));
    return a;
}
__device__ __forceinline__ void cpa16(uint32_t dst, const void* src) {
    asm volatile("cp.async.cg.shared.global [%0], [%1], 16;" :: "r"(dst), "l"(src));
}

#define PLANE_BYTES (128 * LDT * 2)            // 10240
#define OFF_AH 0
#define OFF_AL (PLANE_BYTES)
#define OFF_BH (2 * PLANE_BYTES)
#define OFF_BL (3 * PLANE_BYTES)
#define STAGE_BYTES (4 * PLANE_BYTES)          // 40960
#define SMEM_TOTAL (2 * STAGE_BYTES)           // 81920

__global__ __launch_bounds__(256) void k_gemm_mma(
    const __nv_bfloat16* __restrict__ Ah, const __nv_bfloat16* __restrict__ Al,
    const __nv_bfloat16* __restrict__ Xh, const __nv_bfloat16* __restrict__ Xl,
    const __nv_bfloat16* __restrict__ Wh, const __nv_bfloat16* __restrict__ Wl,
    const float* __restrict__ bias, float* __restrict__ out,
    __nv_bfloat16* __restrict__ Hh, __nv_bfloat16* __restrict__ Hl,   // layer-1 extras (or null)
    int n, int outc, int do_relu)
{
    extern __shared__ char smem[];
    const uint32_t sb0 = smem_u32(smem);

    const int tid  = threadIdx.x;
    const int wid  = tid >> 5;
    const int lane = tid & 31;
    const int g    = lane >> 2;
    const int t    = lane & 3;
    const int m0   = blockIdx.x * 128;
    const int n0   = blockIdx.y * 128;
    const int warpM = (wid & 3) * 32;
    const int warpN = (wid >> 2) * 64;

    // staging map: 2 threads per row, 32B each
    const int srow = tid >> 1;
    const int shalf = tid & 1;
    int anode = m0 + srow; if (anode >= n) anode = n - 1;
    const size_t aoffA = (size_t)anode * KA;
    const size_t aoffX = (size_t)anode * 256;
    const size_t boff  = (size_t)(n0 + srow) * KTOT;
    const uint32_t sdst = srow * (LDT * 2) + shalf * 32;

#define STAGE(KT, STG) do {                                                    \
        int kbase_ = (KT) * BK;                                                \
        uint32_t sb_ = sb0 + (STG) * STAGE_BYTES + sdst;                       \
        const char* pah_; const char* pal_;                                    \
        if (kbase_ < KA) {                                                     \
            pah_ = (const char*)(Ah + aoffA + kbase_) + shalf * 32;            \
            pal_ = (const char*)(Al + aoffA + kbase_) + shalf * 32;            \
        } else {                                                               \
            pah_ = (const char*)(Xh + aoffX + (kbase_ - KA)) + shalf * 32;     \
            pal_ = (const char*)(Xl + aoffX + (kbase_ - KA)) + shalf * 32;     \
        }                                                                      \
        const char* pbh_ = (const char*)(Wh + boff + kbase_) + shalf * 32;     \
        const char* pbl_ = (const char*)(Wl + boff + kbase_) + shalf * 32;     \
        cpa16(sb_ + OFF_AH,      pah_);      cpa16(sb_ + OFF_AH + 16, pah_ + 16); \
        cpa16(sb_ + OFF_AL,      pal_);      cpa16(sb_ + OFF_AL + 16, pal_ + 16); \
        cpa16(sb_ + OFF_BH,      pbh_);      cpa16(sb_ + OFF_BH + 16, pbh_ + 16); \
        cpa16(sb_ + OFF_BL,      pbl_);      cpa16(sb_ + OFF_BL + 16, pbl_ + 16); \
        asm volatile("cp.async.commit_group;");                                \
    } while (0)

    float acc[2][8][4];
#pragma unroll
    for (int mi = 0; mi < 2; ++mi)
#pragma unroll
        for (int ni = 0; ni < 8; ++ni)
#pragma unroll
            for (int c = 0; c < 4; ++c) acc[mi][ni][c] = 0.0f;

    const int KT = KTOT / BK;   // 72
    STAGE(0, 0);

    for (int kt = 0; kt < KT; ++kt) {
        int cur = kt & 1;
        if (kt + 1 < KT) {
            STAGE(kt + 1, cur ^ 1);
            asm volatile("cp.async.wait_group 1;");
        } else {
            asm volatile("cp.async.wait_group 0;");
        }
        __syncthreads();

        const __nv_bfloat16* sAh = (const __nv_bfloat16*)(smem + cur * STAGE_BYTES + OFF_AH);
        const __nv_bfloat16* sAl = (const __nv_bfloat16*)(smem + cur * STAGE_BYTES + OFF_AL);
        const __nv_bfloat16* sBh = (const __nv_bfloat16*)(smem + cur * STAGE_BYTES + OFF_BH);
        const __nv_bfloat16* sBl = (const __nv_bfloat16*)(smem + cur * STAGE_BYTES + OFF_BL);

#pragma unroll
        for (int ks = 0; ks < 2; ++ks) {
            const int kk = ks * 16;
            uint32_t ah[2][4], al[2][4];
#pragma unroll
            for (int mi = 0; mi < 2; ++mi) {
                int r = warpM + mi * 16 + g;
                int o0 = r * LDT + kk + 2 * t;
                int o1 = (r + 8) * LDT + kk + 2 * t;
                ah[mi][0] = *(const uint32_t*)&sAh[o0];
                ah[mi][1] = *(const uint32_t*)&sAh[o1];
                ah[mi][2] = *(const uint32_t*)&sAh[o0 + 8];
                ah[mi][3] = *(const uint32_t*)&sAh[o1 + 8];
                al[mi][0] = *(const uint32_t*)&sAl[o0];
                al[mi][1] = *(const uint32_t*)&sAl[o1];
                al[mi][2] = *(const uint32_t*)&sAl[o0 + 8];
                al[mi][3] = *(const uint32_t*)&sAl[o1 + 8];
            }
#pragma unroll
            for (int ni = 0; ni < 8; ++ni) {
                int c = warpN + ni * 8 + g;
                int o = c * LDT + kk + 2 * t;
                uint32_t b0 = *(const uint32_t*)&sBh[o];
                uint32_t b1 = *(const uint32_t*)&sBh[o + 8];
                uint32_t c0 = *(const uint32_t*)&sBl[o];
                uint32_t c1 = *(const uint32_t*)&sBl[o + 8];
#pragma unroll
                for (int mi = 0; mi < 2; ++mi) {
                    MMA_BF16(acc[mi][ni], ah[mi][0], ah[mi][1], ah[mi][2], ah[mi][3], b0, b1);
                    MMA_BF16(acc[mi][ni], al[mi][0], al[mi][1], al[mi][2], al[mi][3], b0, b1);
                    MMA_BF16(acc[mi][ni], ah[mi][0], ah[mi][1], ah[mi][2], ah[mi][3], c0, c1);
                }
            }
        }
        __syncthreads();
    }

    // --- epilogue ---
#pragma unroll
    for (int mi = 0; mi < 2; ++mi) {
        int r0 = m0 + warpM + mi * 16 + g;
#pragma unroll
        for (int ni = 0; ni < 8; ++ni) {
            int c = n0 + warpN + ni * 8 + 2 * t;
            float b0 = bias[c], b1 = bias[c + 1];
            float v0 = acc[mi][ni][0] + b0;
            float v1 = acc[mi][ni][1] + b1;
            float v2 = acc[mi][ni][2] + b0;
            float v3 = acc[mi][ni][3] + b1;
            if (do_relu) {
                v0 = fmaxf(v0, 0.f); v1 = fmaxf(v1, 0.f);
                v2 = fmaxf(v2, 0.f); v3 = fmaxf(v3, 0.f);
            }
            if (r0 < n) {
                *(float2*)(out + (size_t)r0 * outc + c) = make_float2(v0, v1);
                if (Hh) {
                    __nv_bfloat162 hh = __floats2bfloat162_rn(v0, v1);
                    __nv_bfloat162 ll = __floats2bfloat162_rn(v0 - __low2float(hh),
                                                              v1 - __high2float(hh));
                    *(unsigned*)(Hh + (size_t)r0 * 256 + c) = *(unsigned*)&hh;
                    *(unsigned*)(Hl + (size_t)r0 * 256 + c) = *(unsigned*)&ll;
                }
            }
            if (r0 + 8 < n) {
                *(float2*)(out + (size_t)(r0 + 8) * outc + c) = make_float2(v2, v3);
                if (Hh) {
                    __nv_bfloat162 hh = __floats2bfloat162_rn(v2, v3);
                    __nv_bfloat162 ll = __floats2bfloat162_rn(v2 - __low2float(hh),
                                                              v3 - __high2float(hh));
                    *(unsigned*)(Hh + (size_t)(r0 + 8) * 256 + c) = *(unsigned*)&hh;
                    *(unsigned*)(Hl + (size_t)(r0 + 8) * 256 + c) = *(unsigned*)&ll;
                }
            }
        }
    }
}

// ---------------------------------------------------------------------------
extern "C" void kernel_launch(void* const* d_in, const int* in_sizes, int n_in,
                              void* d_out, int out_size)
{
    const float* x     = (const float*)d_in[0];
    const float* W1    = (const float*)d_in[1];
    const float* root1 = (const float*)d_in[2];
    const float* b1    = (const float*)d_in[3];
    const float* W2    = (const float*)d_in[4];
    const float* root2 = (const float*)d_in[5];
    const float* b2    = (const float*)d_in[6];
    const void*  ei    = d_in[7];
    const void*  et    = d_in[8];

    int E = in_sizes[8];
    int n = in_sizes[0] / 256;
    int nseg = n * R_REL;
    int sblk = (nseg + 255) / 256;

    __nv_bfloat16 *Ah, *Al, *X1h, *X1l, *X2h, *X2l, *Wh1, *Wl1, *Wh2, *Wl2;
    float* h;
    cudaGetSymbolAddress((void**)&Ah,  g_Ah);
    cudaGetSymbolAddress((void**)&Al,  g_Al);
    cudaGetSymbolAddress((void**)&X1h, g_X1h);
    cudaGetSymbolAddress((void**)&X1l, g_X1l);
    cudaGetSymbolAddress((void**)&X2h, g_X2h);
    cudaGetSymbolAddress((void**)&X2l, g_X2l);
    cudaGetSymbolAddress((void**)&Wh1, g_Wh1);
    cudaGetSymbolAddress((void**)&Wl1, g_Wl1);
    cudaGetSymbolAddress((void**)&Wh2, g_Wh2);
    cudaGetSymbolAddress((void**)&Wl2, g_Wl2);
    cudaGetSymbolAddress((void**)&h,   g_h);

    cudaFuncSetAttribute(k_gemm_mma, cudaFuncAttributeMaxDynamicSharedMemorySize, SMEM_TOTAL);

    dim3 g1((n + 127) / 128, 2);
    dim3 g2((n + 127) / 128, 1);

    // CSR build (once; shared by both layers)
    k_detect_zero<<<sblk, 256>>>((const unsigned*)ei, 2 * E, nseg);
    k_count<<<(E + 255) / 256, 256>>>(ei, et, E);
    k_scan1<<<sblk, 256>>>(nseg);
    k_scan2<<<sblk, 256>>>(nseg);
    k_scatter<<<(E + 255) / 256, 256>>>(ei, et, E);

    // ---- layer 1 ----
    k_agg_csr<<<(nseg + 7) / 8, 256>>>(x, Ah, Al, nseg);          // 6th launch (profiled)
    k_wconv<<<(384 * KTOT + 255) / 256, 256>>>(W1, root1, W2, root2);
    k_xconv<<<(n * 256 + 255) / 256, 256>>>(x, n * 256);
    k_gemm_mma<<<g1, 256, SMEM_TOTAL>>>(Ah, Al, X1h, X1l, Wh1, Wl1, b1, h, X2h, X2l, n, 256, 1);

    // ---- layer 2 ----
    k_agg_csr<<<(nseg + 7) / 8, 256>>>(h, Ah, Al, nseg);
    k_gemm_mma<<<g2, 256, SMEM_TOTAL>>>(Ah, Al, X2h, X2l, Wh2, Wl2, b2, (float*)d_out,
                                        (__nv_bfloat16*)nullptr, (__nv_bfloat16*)nullptr,
                                        n, 128, 0);
}